// round 12
// baseline (speedup 1.0000x reference)
#include <cuda_runtime.h>
#include <math.h>

#define N_NODES 20000
#define K_NB    32
#define D_DIM   128
#define PAD     132   // fp32 tile row stride (floats)
#define AHP     68    // fp16 A-tile row stride (u32)
#define N_TILES (N_NODES / 2)

// ---------------- scratch (device globals: allocation-free) ----------------
__device__ float g_tsf[(size_t)N_NODES * D_DIM];   // self_feats @ self_weights
__device__ float g_tself[N_NODES];                 // self_vecs . gate_self_w

__device__ __forceinline__ float sigmoid_tanh(float x) {
    float t;
    asm("tanh.approx.f32 %0, %1;" : "=f"(t) : "f"(0.5f * x));
    return fmaf(0.5f, t, 0.5f);
}

// pack two f32 -> f16x2 (hi = first arg, lo = second arg)
__device__ __forceinline__ unsigned packh(float hi, float lo) {
    unsigned r;
    asm("cvt.rn.f16x2.f32 %0, %1, %2;" : "=r"(r) : "f"(hi), "f"(lo));
    return r;
}

__device__ __forceinline__ void cp16(void* dst, const void* src) {
    unsigned sa = (unsigned)__cvta_generic_to_shared(dst);
    asm volatile("cp.async.cg.shared.global [%0], [%1], 16;\n" :: "r"(sa), "l"(src));
}
__device__ __forceinline__ void cp_commit() {
    asm volatile("cp.async.commit_group;\n");
}
__device__ __forceinline__ void cp_wait0() {
    asm volatile("cp.async.wait_group 0;\n");
}

// fp16 mma m16n8k16, fp32 accumulate
__device__ __forceinline__ void mma_f16(float& c0, float& c1, float& c2, float& c3,
                                        unsigned a0, unsigned a1, unsigned a2, unsigned a3,
                                        unsigned b0, unsigned b1) {
    asm volatile(
        "mma.sync.aligned.m16n8k16.row.col.f32.f16.f16.f32 "
        "{%0,%1,%2,%3}, {%4,%5,%6,%7}, {%8,%9}, {%0,%1,%2,%3};\n"
        : "+f"(c0), "+f"(c1), "+f"(c2), "+f"(c3)
        : "r"(a0), "r"(a1), "r"(a2), "r"(a3), "r"(b0), "r"(b1));
}

// ---------------- kernel 1: tself[n] = dot(self_vecs[n], gate_self_w) ------
__global__ void k_tself(const float* __restrict__ self_vecs,
                        const float* __restrict__ gws) {
    int gtid = blockIdx.x * blockDim.x + threadIdx.x;
    int node = gtid >> 5;
    int lane = gtid & 31;
    if (node >= N_NODES) return;
    float4 a = ((const float4*)(self_vecs + (size_t)node * D_DIM))[lane];
    float4 b = __ldg(&((const float4*)gws)[lane]);
    float s = a.x * b.x + a.y * b.y + a.z * b.z + a.w * b.w;
    #pragma unroll
    for (int o = 16; o > 0; o >>= 1) s += __shfl_down_sync(0xffffffffu, s, o);
    if (lane == 0) g_tself[node] = s;
}

// ---------------- kernel 2: tsf = self_feats @ self_weights ----------------
#define TSF_NODES 16
__global__ void k_tsf(const float* __restrict__ self_feats,
                      const float* __restrict__ Ws) {
    extern __shared__ float sm[];
    float* Wsh = sm;
    float* sfs = sm + D_DIM * D_DIM;
    int t = threadIdx.x;

    for (int i = t; i < (D_DIM * D_DIM) / 4; i += 256)
        ((float4*)Wsh)[i] = ((const float4*)Ws)[i];

    int nbase = blockIdx.x * TSF_NODES;
    const float4* gsf = (const float4*)(self_feats + (size_t)nbase * D_DIM);
    for (int i = t; i < (TSF_NODES * D_DIM) / 4; i += 256)
        ((float4*)sfs)[i] = gsf[i];
    __syncthreads();

    int e = t & 127;
    int g = t >> 7;
    float acc[8];
    #pragma unroll
    for (int m = 0; m < 8; m++) acc[m] = 0.0f;

    #pragma unroll 4
    for (int d = 0; d < D_DIM; d++) {
        float w = Wsh[d * D_DIM + e];
        #pragma unroll
        for (int m = 0; m < 8; m++)
            acc[m] = fmaf(w, sfs[(g * 8 + m) * D_DIM + d], acc[m]);
    }
    #pragma unroll
    for (int m = 0; m < 8; m++)
        g_tsf[(size_t)(nbase + g * 8 + m) * D_DIM + e] = acc[m];
}

// ---------------- k_main building blocks (512 threads) ---------------------

__device__ __forceinline__ void prefetch_lv(int p, float* lvd,
                                            const float* link, int t) {
    if (p < N_TILES) {
        #pragma unroll
        for (int j = 0; j < 4; j++) {
            int idx = t + j * 512;
            int row = idx >> 5, c4 = idx & 31;
            size_t gb = (((size_t)p * 64 + row) << 7) + c4 * 4;
            cp16(lvd + row * PAD + c4 * 4, link + gb);
        }
    }
    cp_commit();
}
__device__ __forceinline__ void prefetch_nv(int p, float* nvd,
                                            const float* neigh, int t) {
    if (p < N_TILES) {
        #pragma unroll
        for (int j = 0; j < 4; j++) {
            int idx = t + j * 512;
            int row = idx >> 5, c4 = idx & 31;
            size_t gb = (((size_t)p * 64 + row) << 7) + c4 * 4;
            cp16(nvd + row * PAD + c4 * 4, neigh + gb);
        }
    }
    cp_commit();
}

__device__ __forceinline__ void ts_load(int p, int wm, int wn, int lane,
                                        float2 (&ts)[2]) {
    if (lane < 4) {
        int node = p * 2 + wm;
        #pragma unroll
        for (int ns = 0; ns < 2; ns++)
            ts[ns] = *(const float2*)&g_tsf[(size_t)node * D_DIM +
                                            wn * 16 + ns * 8 + lane * 2];
    }
}

// convert lv->fp16 ah + lv.gwl partial (pre-GEMM phase)
__device__ __forceinline__ float conv_lvdot(const float* lvs, unsigned* ah,
                                            const float* gwls, int kk, int sub) {
    float s0 = 0.f, s1 = 0.f;
    const float* lr = lvs + kk * PAD;
    unsigned* ar = ah + kk * AHP;
    #pragma unroll
    for (int m = 0; m < 2; m++) {
        int c = 8 * sub + 64 * m;
        float4 a = *(const float4*)(lr + c);
        float4 b = *(const float4*)(gwls + c);
        s0 = fmaf(a.x, b.x, fmaf(a.y, b.y, fmaf(a.z, b.z, fmaf(a.w, b.w, s0))));
        float4 a2 = *(const float4*)(lr + c + 4);
        float4 b2 = *(const float4*)(gwls + c + 4);
        s1 = fmaf(a2.x, b2.x, fmaf(a2.y, b2.y, fmaf(a2.z, b2.z, fmaf(a2.w, b2.w, s1))));
        uint4 ph;
        ph.x = packh(a.y, a.x);
        ph.y = packh(a.w, a.z);
        ph.z = packh(a2.y, a2.x);
        ph.w = packh(a2.w, a2.z);
        *(uint4*)(ar + 4 * sub + 32 * m) = ph;
    }
    return s0 + s1;
}

// nv.gwn partial + gate finalize (post-GEMM phase, overlaps HMMA drain)
__device__ __forceinline__ void nv_gate(const float* nvs, float* cshT,
                                        const float* gwns, int kk, int sub,
                                        float lvsum, float pr, float tf) {
    float s0 = 0.f, s1 = 0.f;
    const float* nr = nvs + kk * PAD;
    #pragma unroll
    for (int m = 0; m < 2; m++) {
        int c = 8 * sub + 64 * m;
        float4 u = *(const float4*)(nr + c);
        float4 v = *(const float4*)(gwns + c);
        s0 = fmaf(u.x, v.x, fmaf(u.y, v.y, fmaf(u.z, v.z, fmaf(u.w, v.w, s0))));
        float4 u2 = *(const float4*)(nr + c + 4);
        float4 v2 = *(const float4*)(gwns + c + 4);
        s1 = fmaf(u2.x, v2.x, fmaf(u2.y, v2.y, fmaf(u2.z, v2.z, fmaf(u2.w, v2.w, s1))));
    }
    float s = lvsum + s0 + s1;
    s += __shfl_down_sync(0xffffffffu, s, 1, 8);
    s += __shfl_down_sync(0xffffffffu, s, 2, 8);
    s += __shfl_down_sync(0xffffffffu, s, 4, 8);
    if (sub == 0) {
        float g = sigmoid_tanh(tf + s);
        cshT[kk] = __fdividef(g, pr) * (1.0f / (float)K_NB);
    }
}

// fp16 GEMM: rows rbase(+8/16/24), cols wn*16..+16, K=128 (8 k16 steps)
__device__ __forceinline__ void do_gemm(const unsigned* ah, const uint4* bf,
                                        int rbase, int lq,
                                        float (&acc0)[2][4], float (&acc1)[2][4]) {
    #pragma unroll
    for (int ns = 0; ns < 2; ns++) {
        acc0[ns][0] = acc0[ns][1] = acc0[ns][2] = acc0[ns][3] = 0.0f;
        acc1[ns][0] = acc1[ns][1] = acc1[ns][2] = acc1[ns][3] = 0.0f;
    }
    const unsigned* r0 = ah + rbase * AHP;
    const unsigned* r1 = ah + (rbase + 8) * AHP;
    const unsigned* r2 = ah + (rbase + 16) * AHP;
    const unsigned* r3 = ah + (rbase + 24) * AHP;

    #pragma unroll
    for (int ks = 0; ks < 8; ks++) {
        int d0 = ks * 8 + lq;
        unsigned a00 = r0[d0], a01 = r1[d0], a02 = r0[d0 + 4], a03 = r1[d0 + 4];
        unsigned a10 = r2[d0], a11 = r3[d0], a12 = r2[d0 + 4], a13 = r3[d0 + 4];
        uint4 B = bf[ks * 32];
        mma_f16(acc0[0][0], acc0[0][1], acc0[0][2], acc0[0][3], a00, a01, a02, a03, B.x, B.y);
        mma_f16(acc0[1][0], acc0[1][1], acc0[1][2], acc0[1][3], a00, a01, a02, a03, B.z, B.w);
        mma_f16(acc1[0][0], acc1[0][1], acc1[0][2], acc1[0][3], a10, a11, a12, a13, B.x, B.y);
        mma_f16(acc1[1][0], acc1[1][1], acc1[1][2], acc1[1][3], a10, a11, a12, a13, B.z, B.w);
    }
}

// epilogue for tile p: reduce over 32 rows, scale, relu, store
__device__ __forceinline__ void do_epi(int p, const float (&acc0)[2][4],
                                       const float (&acc1)[2][4],
                                       const float* csh, const float* nvs,
                                       const float2 (&ts)[2], float* out,
                                       int rbase, int wm, int wn, int lane, int lq) {
    float cA = csh[rbase];
    float cB = csh[rbase + 8];
    float cC = csh[rbase + 16];
    float cD = csh[rbase + 24];

    float ps[4];
    #pragma unroll
    for (int ns = 0; ns < 2; ns++) {
        int e0 = wn * 16 + ns * 8 + lq * 2;
        float2 nv0 = *(const float2*)&nvs[rbase * PAD + e0];
        float2 nv1 = *(const float2*)&nvs[(rbase + 8) * PAD + e0];
        float2 nv2 = *(const float2*)&nvs[(rbase + 16) * PAD + e0];
        float2 nv3 = *(const float2*)&nvs[(rbase + 24) * PAD + e0];
        ps[ns * 2 + 0] = sigmoid_tanh(acc0[ns][0]) * nv0.x * cA +
                         sigmoid_tanh(acc0[ns][2]) * nv1.x * cB +
                         sigmoid_tanh(acc1[ns][0]) * nv2.x * cC +
                         sigmoid_tanh(acc1[ns][2]) * nv3.x * cD;
        ps[ns * 2 + 1] = sigmoid_tanh(acc0[ns][1]) * nv0.y * cA +
                         sigmoid_tanh(acc0[ns][3]) * nv1.y * cB +
                         sigmoid_tanh(acc1[ns][1]) * nv2.y * cC +
                         sigmoid_tanh(acc1[ns][3]) * nv3.y * cD;
    }
    #pragma unroll
    for (int o = 4; o <= 16; o <<= 1) {
        #pragma unroll
        for (int i = 0; i < 4; i++)
            ps[i] += __shfl_xor_sync(0xffffffffu, ps[i], o);
    }
    if (lane < 4) {
        int node = p * 2 + wm;
        float* op = out + (size_t)node * D_DIM + wn * 16 + lane * 2;
        #pragma unroll
        for (int ns = 0; ns < 2; ns++) {
            float2 r;
            r.x = fmaxf(ts[ns].x * ps[ns * 2 + 0], 0.0f);
            r.y = fmaxf(ts[ns].y * ps[ns * 2 + 1], 0.0f);
            *(float2*)&op[ns * 8] = r;
        }
    }
}

// ---------------- kernel 3: main (fp16 tensor, 512 thr, pipelined) ---------
// 512 threads = 16 warps, warp grid 2(M) x 8(N). Tile = 2 nodes (64 rows).
// Per iter: convert+lvdot(p) -> GEMM(p) issue -> nv_gate(p) + epilogue(p-1)
// overlapping the HMMA drain; acc/csh/nv ping-pong; lv single-buffered.
__global__ void __launch_bounds__(512, 1)
k_main(const float* __restrict__ neigh,
       const float* __restrict__ link,
       const float* __restrict__ probs,
       const float* __restrict__ gwn,
       const float* __restrict__ gwl,
       const float* __restrict__ Wl,
       float* __restrict__ out) {
    extern __shared__ float sm[];
    float*    bfrag = sm;                          // 8192 u32 (32 KB)
    float*    lvb   = bfrag + 8192;                // 64*132
    float*    nvb0  = lvb + 64 * PAD;
    float*    nvb1  = nvb0 + 64 * PAD;
    unsigned* ah    = (unsigned*)(nvb1 + 64 * PAD);// 64*68 u32 (17 KB)
    float*    csh0  = (float*)(ah + 64 * AHP);     // 64
    float*    csh1  = csh0 + 64;                   // 64
    float*    gwns  = csh1 + 64;                   // 128
    float*    gwls  = gwns + D_DIM;                // 128

    int t = threadIdx.x;
    int warp = t >> 5, lane = t & 31;
    int wm = warp >> 3, wn = warp & 7;             // 2 x 8
    int lp = lane >> 2;
    int lq = lane & 3;
    int rbase = wm * 32 + lp;
    int kk = t >> 3, sub = t & 7;                  // gate: 64 rows x 8 subs
    int G = gridDim.x;

    // ---- prologue prefetch of tile p0 (lv + nv0)
    int p0 = blockIdx.x;
    if (p0 < N_TILES) {
        #pragma unroll
        for (int j = 0; j < 4; j++) {
            int idx = t + j * 512;
            int row = idx >> 5, c4 = idx & 31;
            size_t gb = (((size_t)p0 * 64 + row) << 7) + c4 * 4;
            cp16(lvb + row * PAD + c4 * 4, link + gb);
            cp16(nvb0 + row * PAD + c4 * 4, neigh + gb);
        }
    }
    cp_commit();

    if (t < D_DIM) { gwns[t] = gwn[t]; gwls[t] = gwl[t]; }

    // ---- build fp16 B fragments in mma order (one-time, 8192 u32)
    // i = (((wnb*8+ks)*32)+ln)*4 + j ;  ns = j>>1
    // kb = ks*16 + 2*llq + 8*(j&1) ;  n = wnb*16 + ns*8 + llp
    for (int i = t; i < 8192; i += 512) {
        int j   = i & 3;
        int ln  = (i >> 2) & 31;
        int ks  = (i >> 7) & 7;
        int wnb = (i >> 10) & 7;
        int llq = ln & 3, llp = ln >> 2;
        int ns  = j >> 1;
        int kb  = ks * 16 + 2 * llq + 8 * (j & 1);
        int n   = wnb * 16 + ns * 8 + llp;
        ((unsigned*)bfrag)[i] = packh(__ldg(&Wl[(kb + 1) * D_DIM + n]),
                                      __ldg(&Wl[kb * D_DIM + n]));
    }
    const uint4* bf = (const uint4*)bfrag + (wn * 8) * 32 + lane;

    float accA0[2][4], accA1[2][4], accB0[2][4], accB1[2][4];
    float2 ts_prev[2];

    // ---- prologue compute for tile p0
    {
        float pr = 0.f, tf = 0.f;
        if (sub == 0) {
            pr = __ldg(&probs[(size_t)p0 * 64 + kk]);
            tf = g_tself[p0 * 2 + (kk >> 5)];
        }
        cp_wait0();
        __syncthreads();                 // tile p0 + bfrag + gw ready
        float lvsum = conv_lvdot(lvb, ah, gwls, kk, sub);
        __syncthreads();                 // ah visible; lv stage free
        prefetch_lv(p0 + G, lvb, link, t);
        do_gemm(ah, bf, rbase, lq, accA0, accA1);
        nv_gate(nvb0, csh0, gwns, kk, sub, lvsum, pr, tf);
        ts_load(p0, wm, wn, lane, ts_prev);
        prefetch_nv(p0 + G, nvb1, neigh, t);
    }

    int p = p0;
    int phase = 1;     // buffers of the NEXT tile (pn): 1 -> nv1/csh1/accB
    for (int pn = p0 + G; pn < N_TILES; pn += G) {
        float pr = 0.f, tf = 0.f;
        if (sub == 0) {
            pr = __ldg(&probs[(size_t)pn * 64 + kk]);
            tf = g_tself[pn * 2 + (kk >> 5)];
        }
        cp_wait0();
        __syncthreads();                 // tile pn (lv + nv[phase]) ready
        if (phase) {
            float lvsum = conv_lvdot(lvb, ah, gwls, kk, sub);
            __syncthreads();             // ah visible; lv stage free
            prefetch_lv(pn + G, lvb, link, t);
            do_gemm(ah, bf, rbase, lq, accB0, accB1);
            nv_gate(nvb1, csh1, gwns, kk, sub, lvsum, pr, tf);
            do_epi(p, accA0, accA1, csh0, nvb0, ts_prev, out,
                   rbase, wm, wn, lane, lq);
            ts_load(pn, wm, wn, lane, ts_prev);
            __syncthreads();             // nvb0/csh0 reads done
            prefetch_nv(pn + G, nvb0, neigh, t);
        } else {
            float lvsum = conv_lvdot(lvb, ah, gwls, kk, sub);
            __syncthreads();
            prefetch_lv(pn + G, lvb, link, t);
            do_gemm(ah, bf, rbase, lq, accA0, accA1);
            nv_gate(nvb0, csh0, gwns, kk, sub, lvsum, pr, tf);
            do_epi(p, accB0, accB1, csh1, nvb1, ts_prev, out,
                   rbase, wm, wn, lane, lq);
            ts_load(pn, wm, wn, lane, ts_prev);
            __syncthreads();
            prefetch_nv(pn + G, nvb1, neigh, t);
        }
        p = pn;
        phase ^= 1;
    }

    // final pending epilogue: last tile used phase^1
    if (phase)
        do_epi(p, accA0, accA1, csh0, nvb0, ts_prev, out, rbase, wm, wn, lane, lq);
    else
        do_epi(p, accB0, accB1, csh1, nvb1, ts_prev, out, rbase, wm, wn, lane, lq);
}

// ---------------- launch ----------------------------------------------------
extern "C" void kernel_launch(void* const* d_in, const int* in_sizes, int n_in,
                              void* d_out, int out_size) {
    const float* self_feats = (const float*)d_in[0];
    const float* self_vecs  = (const float*)d_in[1];
    const float* neigh      = (const float*)d_in[2];
    const float* link       = (const float*)d_in[3];
    const float* probs      = (const float*)d_in[4];
    const float* gws        = (const float*)d_in[5];
    const float* gwn        = (const float*)d_in[6];
    const float* gwl        = (const float*)d_in[7];
    const float* Ws         = (const float*)d_in[8];
    const float* Wl         = (const float*)d_in[9];
    float* out = (float*)d_out;

    const int smem_tsf  = (D_DIM * D_DIM + TSF_NODES * D_DIM) * sizeof(float); // 72 KB
    const int smem_main = (8192 + 3 * 64 * PAD + 64 * AHP + 2 * 64 +
                           2 * D_DIM) * sizeof(float);                         // ~153 KB

    cudaFuncSetAttribute(k_tsf,  cudaFuncAttributeMaxDynamicSharedMemorySize, smem_tsf);
    cudaFuncSetAttribute(k_main, cudaFuncAttributeMaxDynamicSharedMemorySize, smem_main);

    k_tself<<<(N_NODES * 32 + 255) / 256, 256>>>(self_vecs, gws);
    k_tsf<<<N_NODES / TSF_NODES, 256, smem_tsf>>>(self_feats, Ws);
    k_main<<<148, 512, smem_main>>>(neigh, link, probs, gwn, gwl, Wl, out);
}

// round 13
// speedup vs baseline: 1.1899x; 1.1899x over previous
#include <cuda_runtime.h>
#include <cuda_fp16.h>
#include <math.h>

#define N_NODES 20000
#define K_NB    32
#define D_DIM   128
#define PAD     132   // fp32 staging row stride (floats)
#define AHP     68    // fp16 A-tile row stride (u32)
#define STRIDE_BUF (64 * PAD)   // one staging buffer: lv(32*PAD) + nv(32*PAD)

// ---------------- scratch (device globals: allocation-free) ----------------
__device__ float g_tsf[(size_t)N_NODES * D_DIM];   // self_feats @ self_weights
__device__ float g_tself[N_NODES];                 // self_vecs . gate_self_w

__device__ __forceinline__ float sigmoid_tanh(float x) {
    float t;
    asm("tanh.approx.f32 %0, %1;" : "=f"(t) : "f"(0.5f * x));
    return fmaf(0.5f, t, 0.5f);
}

// pack two f32 -> f16x2 (hi = first arg, lo = second arg)
__device__ __forceinline__ unsigned packh(float hi, float lo) {
    unsigned r;
    asm("cvt.rn.f16x2.f32 %0, %1, %2;" : "=r"(r) : "f"(hi), "f"(lo));
    return r;
}

__device__ __forceinline__ void cp16(void* dst, const void* src) {
    unsigned sa = (unsigned)__cvta_generic_to_shared(dst);
    asm volatile("cp.async.cg.shared.global [%0], [%1], 16;\n" :: "r"(sa), "l"(src));
}
__device__ __forceinline__ void cp_commit() {
    asm volatile("cp.async.commit_group;\n");
}
__device__ __forceinline__ void cp_wait0() {
    asm volatile("cp.async.wait_group 0;\n");
}

// fp16 mma m16n8k16, fp32 accumulate
__device__ __forceinline__ void mma_f16(float& c0, float& c1, float& c2, float& c3,
                                        unsigned a0, unsigned a1, unsigned a2, unsigned a3,
                                        unsigned b0, unsigned b1) {
    asm volatile(
        "mma.sync.aligned.m16n8k16.row.col.f32.f16.f16.f32 "
        "{%0,%1,%2,%3}, {%4,%5,%6,%7}, {%8,%9}, {%0,%1,%2,%3};\n"
        : "+f"(c0), "+f"(c1), "+f"(c2), "+f"(c3)
        : "r"(a0), "r"(a1), "r"(a2), "r"(a3), "r"(b0), "r"(b1));
}

// ---------------- kernel 1: tself[n] = dot(self_vecs[n], gate_self_w) ------
__global__ void k_tself(const float* __restrict__ self_vecs,
                        const float* __restrict__ gws) {
    int gtid = blockIdx.x * blockDim.x + threadIdx.x;
    int node = gtid >> 5;
    int lane = gtid & 31;
    if (node >= N_NODES) return;
    float4 a = ((const float4*)(self_vecs + (size_t)node * D_DIM))[lane];
    float4 b = __ldg(&((const float4*)gws)[lane]);
    float s = a.x * b.x + a.y * b.y + a.z * b.z + a.w * b.w;
    #pragma unroll
    for (int o = 16; o > 0; o >>= 1) s += __shfl_down_sync(0xffffffffu, s, o);
    if (lane == 0) g_tself[node] = s;
}

// ---------------- kernel 2: tsf = self_feats @ self_weights ----------------
#define TSF_NODES 16
__global__ void k_tsf(const float* __restrict__ self_feats,
                      const float* __restrict__ Ws) {
    extern __shared__ float sm[];
    float* Wsh = sm;
    float* sfs = sm + D_DIM * D_DIM;
    int t = threadIdx.x;

    for (int i = t; i < (D_DIM * D_DIM) / 4; i += 256)
        ((float4*)Wsh)[i] = ((const float4*)Ws)[i];

    int nbase = blockIdx.x * TSF_NODES;
    const float4* gsf = (const float4*)(self_feats + (size_t)nbase * D_DIM);
    for (int i = t; i < (TSF_NODES * D_DIM) / 4; i += 256)
        ((float4*)sfs)[i] = gsf[i];
    __syncthreads();

    int e = t & 127;
    int g = t >> 7;
    float acc[8];
    #pragma unroll
    for (int m = 0; m < 8; m++) acc[m] = 0.0f;

    #pragma unroll 4
    for (int d = 0; d < D_DIM; d++) {
        float w = Wsh[d * D_DIM + e];
        #pragma unroll
        for (int m = 0; m < 8; m++)
            acc[m] = fmaf(w, sfs[(g * 8 + m) * D_DIM + d], acc[m]);
    }
    #pragma unroll
    for (int m = 0; m < 8; m++)
        g_tsf[(size_t)(nbase + g * 8 + m) * D_DIM + e] = acc[m];
}

// ---------------- k_main building blocks (256 thr, 1-node tiles) -----------

// prefetch one node tile (lv + nv, 32 rows x 128) into a staging buffer
__device__ __forceinline__ void prefetch_tile(int p, float* buf,
                                              const float* link,
                                              const float* neigh, int t) {
    if (p < N_NODES) {
        #pragma unroll
        for (int j = 0; j < 4; j++) {
            int idx = t + j * 256;              // 0..1023
            int row = idx >> 5, c4 = idx & 31;  // row 0..31, col-chunk 0..31
            size_t gb = (((size_t)p * 32 + row) << 7) + c4 * 4;
            cp16(buf + row * PAD + c4 * 4, link + gb);
            cp16(buf + 32 * PAD + row * PAD + c4 * 4, neigh + gb);
        }
    }
    cp_commit();
}

__device__ __forceinline__ void ts_load(int p, int wn, int lane,
                                        float2 (&ts)[2]) {
    if (lane < 4) {
        #pragma unroll
        for (int ns = 0; ns < 2; ns++)
            ts[ns] = *(const float2*)&g_tsf[(size_t)p * D_DIM +
                                            wn * 16 + ns * 8 + lane * 2];
    }
}

// convert lv->fp16 ah + lv.gwl partial (rows kk=0..31, 8 subs of 16 cols)
__device__ __forceinline__ float conv_lvdot(const float* lvs, unsigned* ah,
                                            const float* gwls, int kk, int sub) {
    float s0 = 0.f, s1 = 0.f;
    const float* lr = lvs + kk * PAD;
    unsigned* ar = ah + kk * AHP;
    #pragma unroll
    for (int m = 0; m < 2; m++) {
        int c = 8 * sub + 64 * m;
        float4 a = *(const float4*)(lr + c);
        float4 b = *(const float4*)(gwls + c);
        s0 = fmaf(a.x, b.x, fmaf(a.y, b.y, fmaf(a.z, b.z, fmaf(a.w, b.w, s0))));
        float4 a2 = *(const float4*)(lr + c + 4);
        float4 b2 = *(const float4*)(gwls + c + 4);
        s1 = fmaf(a2.x, b2.x, fmaf(a2.y, b2.y, fmaf(a2.z, b2.z, fmaf(a2.w, b2.w, s1))));
        uint4 ph;
        ph.x = packh(a.y, a.x);
        ph.y = packh(a.w, a.z);
        ph.z = packh(a2.y, a2.x);
        ph.w = packh(a2.w, a2.z);
        *(uint4*)(ar + 4 * sub + 32 * m) = ph;
    }
    return s0 + s1;
}

// nv.gwn partial + gate finalize
__device__ __forceinline__ void nv_gate(const float* nvs, float* cshT,
                                        const float* gwns, int kk, int sub,
                                        float lvsum, float pr, float tf) {
    float s0 = 0.f, s1 = 0.f;
    const float* nr = nvs + kk * PAD;
    #pragma unroll
    for (int m = 0; m < 2; m++) {
        int c = 8 * sub + 64 * m;
        float4 u = *(const float4*)(nr + c);
        float4 v = *(const float4*)(gwns + c);
        s0 = fmaf(u.x, v.x, fmaf(u.y, v.y, fmaf(u.z, v.z, fmaf(u.w, v.w, s0))));
        float4 u2 = *(const float4*)(nr + c + 4);
        float4 v2 = *(const float4*)(gwns + c + 4);
        s1 = fmaf(u2.x, v2.x, fmaf(u2.y, v2.y, fmaf(u2.z, v2.z, fmaf(u2.w, v2.w, s1))));
    }
    float s = lvsum + s0 + s1;
    s += __shfl_down_sync(0xffffffffu, s, 1, 8);
    s += __shfl_down_sync(0xffffffffu, s, 2, 8);
    s += __shfl_down_sync(0xffffffffu, s, 4, 8);
    if (sub == 0) {
        float g = sigmoid_tanh(tf + s);
        cshT[kk] = __fdividef(g, pr) * (1.0f / (float)K_NB);
    }
}

// fp16 GEMM: warp covers all 32 rows (lp, +8, +16, +24), cols wn*16..+16
__device__ __forceinline__ void do_gemm(const unsigned* ah, const uint4* bf,
                                        int lp, int lq,
                                        float (&acc0)[2][4], float (&acc1)[2][4]) {
    #pragma unroll
    for (int ns = 0; ns < 2; ns++) {
        acc0[ns][0] = acc0[ns][1] = acc0[ns][2] = acc0[ns][3] = 0.0f;
        acc1[ns][0] = acc1[ns][1] = acc1[ns][2] = acc1[ns][3] = 0.0f;
    }
    const unsigned* r0 = ah + lp * AHP;
    const unsigned* r1 = ah + (lp + 8) * AHP;
    const unsigned* r2 = ah + (lp + 16) * AHP;
    const unsigned* r3 = ah + (lp + 24) * AHP;

    #pragma unroll
    for (int ks = 0; ks < 8; ks++) {
        int d0 = ks * 8 + lq;
        unsigned a00 = r0[d0], a01 = r1[d0], a02 = r0[d0 + 4], a03 = r1[d0 + 4];
        unsigned a10 = r2[d0], a11 = r3[d0], a12 = r2[d0 + 4], a13 = r3[d0 + 4];
        uint4 B = bf[ks * 32];
        mma_f16(acc0[0][0], acc0[0][1], acc0[0][2], acc0[0][3], a00, a01, a02, a03, B.x, B.y);
        mma_f16(acc0[1][0], acc0[1][1], acc0[1][2], acc0[1][3], a00, a01, a02, a03, B.z, B.w);
        mma_f16(acc1[0][0], acc1[0][1], acc1[0][2], acc1[0][3], a10, a11, a12, a13, B.x, B.y);
        mma_f16(acc1[1][0], acc1[1][1], acc1[1][2], acc1[1][3], a10, a11, a12, a13, B.z, B.w);
    }
}

// epilogue: reduce over all 32 rows (in-warp), scale, relu, store
__device__ __forceinline__ void do_epi(int p, const float (&acc0)[2][4],
                                       const float (&acc1)[2][4],
                                       const float* csh, const float* nvs,
                                       const float2 (&ts)[2], float* out,
                                       int lp, int wn, int lane, int lq) {
    float cA = csh[lp];
    float cB = csh[lp + 8];
    float cC = csh[lp + 16];
    float cD = csh[lp + 24];

    float ps[4];
    #pragma unroll
    for (int ns = 0; ns < 2; ns++) {
        int e0 = wn * 16 + ns * 8 + lq * 2;
        float2 nv0 = *(const float2*)&nvs[lp * PAD + e0];
        float2 nv1 = *(const float2*)&nvs[(lp + 8) * PAD + e0];
        float2 nv2 = *(const float2*)&nvs[(lp + 16) * PAD + e0];
        float2 nv3 = *(const float2*)&nvs[(lp + 24) * PAD + e0];
        ps[ns * 2 + 0] = sigmoid_tanh(acc0[ns][0]) * nv0.x * cA +
                         sigmoid_tanh(acc0[ns][2]) * nv1.x * cB +
                         sigmoid_tanh(acc1[ns][0]) * nv2.x * cC +
                         sigmoid_tanh(acc1[ns][2]) * nv3.x * cD;
        ps[ns * 2 + 1] = sigmoid_tanh(acc0[ns][1]) * nv0.y * cA +
                         sigmoid_tanh(acc0[ns][3]) * nv1.y * cB +
                         sigmoid_tanh(acc1[ns][1]) * nv2.y * cC +
                         sigmoid_tanh(acc1[ns][3]) * nv3.y * cD;
    }
    #pragma unroll
    for (int o = 4; o <= 16; o <<= 1) {
        #pragma unroll
        for (int i = 0; i < 4; i++)
            ps[i] += __shfl_xor_sync(0xffffffffu, ps[i], o);
    }
    if (lane < 4) {
        float* op = out + (size_t)p * D_DIM + wn * 16 + lane * 2;
        #pragma unroll
        for (int ns = 0; ns < 2; ns++) {
            float2 r;
            r.x = fmaxf(ts[ns].x * ps[ns * 2 + 0], 0.0f);
            r.y = fmaxf(ts[ns].y * ps[ns * 2 + 1], 0.0f);
            *(float2*)&op[ns * 8] = r;
        }
    }
}

// ---------------- kernel 3: main (fp16 tensor, 2 CTAs/SM) ------------------
// 256 threads = 8 warps, warp grid 1(M) x 8(N). Tile = 1 node (32 rows).
// No intra-CTA pipelining: the co-resident CTA hides latency. cp.async
// double-buffered raw staging (lv+nv); smem ~110 KB -> 2 CTAs/SM.
__global__ void __launch_bounds__(256, 2)
k_main(const float* __restrict__ neigh,
       const float* __restrict__ link,
       const float* __restrict__ probs,
       const float* __restrict__ gwn,
       const float* __restrict__ gwl,
       const float* __restrict__ Wl,
       float* __restrict__ out) {
    extern __shared__ float sm[];
    float*    bfrag = sm;                              // 8192 u32 (32 KB)
    float*    stage = bfrag + 8192;                    // 2 * 64*PAD fp32
    unsigned* ah    = (unsigned*)(stage + 2 * 64 * PAD);  // 32*68 u32
    float*    csh   = (float*)(ah + 32 * AHP);         // 32
    float*    gwns  = csh + 32;                        // 128
    float*    gwls  = gwns + D_DIM;                    // 128

    int t = threadIdx.x;
    int warp = t >> 5, lane = t & 31;
    int wn = warp;                        // 8 N-groups of 16 cols
    int lp = lane >> 2;
    int lq = lane & 3;
    int kk = t >> 3, sub = t & 7;         // gate: 32 rows x 8 subs
    int G = gridDim.x;

    // ---- prologue prefetch of tile p0
    int p0 = blockIdx.x;
    prefetch_tile(p0, stage, link, neigh, t);

    if (t < D_DIM) { gwns[t] = gwn[t]; gwls[t] = gwl[t]; }

    // ---- build fp16 B fragments in mma order (one-time, 8192 u32)
    // i = (((wnb*8+ks)*32)+ln)*4 + j ;  ns = j>>1
    // kb = ks*16 + 2*llq + 8*(j&1) ;  n = wnb*16 + ns*8 + llp
    for (int i = t; i < 8192; i += 256) {
        int j   = i & 3;
        int ln  = (i >> 2) & 31;
        int ks  = (i >> 7) & 7;
        int wnb = (i >> 10) & 7;
        int llq = ln & 3, llp = ln >> 2;
        int ns  = j >> 1;
        int kb  = ks * 16 + 2 * llq + 8 * (j & 1);
        int n   = wnb * 16 + ns * 8 + llp;
        ((unsigned*)bfrag)[i] = packh(__ldg(&Wl[(kb + 1) * D_DIM + n]),
                                      __ldg(&Wl[kb * D_DIM + n]));
    }
    const uint4* bf = (const uint4*)bfrag + (wn * 8) * 32 + lane;

    float acc0[2][4], acc1[2][4];
    float2 ts[2];

    int buf = 0;
    for (int p = p0; p < N_NODES; p += G) {
        // prefetch per-iter scalars (overlap LDG latency with wait/sync)
        float pr = 0.f, tf = 0.f;
        if (sub == 0) {
            pr = __ldg(&probs[(size_t)p * K_NB + kk]);
            tf = g_tself[p];
        }
        ts_load(p, wn, lane, ts);

        cp_wait0();
        __syncthreads();                 // tile p staged; prev epi reads done

        // issue prefetch of next tile into the other buffer
        prefetch_tile(p + G, stage + (buf ^ 1) * STRIDE_BUF, link, neigh, t);

        const float* lvs = stage + buf * STRIDE_BUF;
        const float* nvs = lvs + 32 * PAD;

        float lvsum = conv_lvdot(lvs, ah, gwls, kk, sub);
        nv_gate(nvs, csh, gwns, kk, sub, lvsum, pr, tf);
        __syncthreads();                 // ah + csh visible

        do_gemm(ah, bf, lp, lq, acc0, acc1);
        do_epi(p, acc0, acc1, csh, nvs, ts, out, lp, wn, lane, lq);

        buf ^= 1;
    }
}

// ---------------- launch ----------------------------------------------------
extern "C" void kernel_launch(void* const* d_in, const int* in_sizes, int n_in,
                              void* d_out, int out_size) {
    const float* self_feats = (const float*)d_in[0];
    const float* self_vecs  = (const float*)d_in[1];
    const float* neigh      = (const float*)d_in[2];
    const float* link       = (const float*)d_in[3];
    const float* probs      = (const float*)d_in[4];
    const float* gws        = (const float*)d_in[5];
    const float* gwn        = (const float*)d_in[6];
    const float* gwl        = (const float*)d_in[7];
    const float* Ws         = (const float*)d_in[8];
    const float* Wl         = (const float*)d_in[9];
    float* out = (float*)d_out;

    const int smem_tsf  = (D_DIM * D_DIM + TSF_NODES * D_DIM) * sizeof(float); // 72 KB
    const int smem_main = (8192 + 2 * 64 * PAD + 32 * AHP + 32 +
                           2 * D_DIM) * sizeof(float);                         // ~110 KB

    cudaFuncSetAttribute(k_tsf,  cudaFuncAttributeMaxDynamicSharedMemorySize, smem_tsf);
    cudaFuncSetAttribute(k_main, cudaFuncAttributeMaxDynamicSharedMemorySize, smem_main);

    k_tself<<<(N_NODES * 32 + 255) / 256, 256>>>(self_vecs, gws);
    k_tsf<<<N_NODES / TSF_NODES, 256, smem_tsf>>>(self_feats, Ws);
    k_main<<<296, 256, smem_main>>>(neigh, link, probs, gwn, gwl, Wl, out);
}